// round 12
// baseline (speedup 1.0000x reference)
#include <cuda_runtime.h>
#include <cuda_bf16.h>

#define BB 512
#define TT 512
#define LL 128
#define PADL 0
#define BOSL 1
#define EOSL 2
#define NB 4          // batches per CTA

typedef unsigned long long ull;

// per-batch (logZ - gold); reduced by second kernel
__device__ float g_res[BB];

#define FMA2(d, a, b, c) \
    asm("fma.rn.f32x2 %0, %1, %2, %3;" : "=l"(d) : "l"(a), "l"(b), "l"(c))
#define ADD2(d, a, b) \
    asm("add.rn.f32x2 %0, %1, %2;" : "=l"(d) : "l"(a), "l"(b))

__device__ __forceinline__ ull pack2(float lo, float hi) {
    ull r;
    asm("mov.b64 %0, {%1, %2};" : "=l"(r) : "f"(lo), "f"(hi));
    return r;
}
__device__ __forceinline__ void unpack2(float& lo, float& hi, ull v) {
    asm("mov.b64 {%0, %1}, %2;" : "=f"(lo), "=f"(hi) : "l"(v));
}

__global__ __launch_bounds__(128, 1) void crf_fwd(
    const float* __restrict__ feat,   // [B, T, L] f32
    const int* __restrict__ tags,     // [B, T] i32
    const int* __restrict__ mask,     // [B, T] i32 (bool widened)
    const float* __restrict__ tr)     // [L, L] f32
{
    const int j    = threadIdx.x;   // label column 0..127
    const int b0   = blockIdx.x * NB;
    const int lane = j & 31;
    const int wid  = j >> 5;

    __shared__ __align__(16) float u_sh[2][NB][LL];  // [buf][batch][i]
    __shared__ float c_sh[2][NB];
    __shared__ int   s_len[NB];
    __shared__ float s_red[NB][4];
    __shared__ float s_gold[NB];

    // ---- E column j packed: E2[m] = (exp(tr[2m][j]), exp(tr[2m+1][j]))
    ull E2[64];
#pragma unroll
    for (int m = 0; m < 64; m++) {
        float lo = __expf(tr[(2 * m)     * LL + j]);
        float hi = __expf(tr[(2 * m + 1) * LL + j]);
        E2[m] = pack2(lo, hi);
    }

    // ---- sequence lengths (mask is a monotone prefix)
    if (j < NB) s_len[j] = 0;
    __syncthreads();
#pragma unroll
    for (int b = 0; b < NB; b++) {
        int cnt = 0;
        for (int t = j; t < TT; t += 128) cnt += (mask[(b0 + b) * TT + t] != 0) ? 1 : 0;
#pragma unroll
        for (int o = 16; o > 0; o >>= 1) cnt += __shfl_down_sync(0xffffffffu, cnt, o);
        if (lane == 0) atomicAdd(&s_len[b], cnt);
    }
    __syncthreads();
    int len[NB];
#pragma unroll
    for (int b = 0; b < NB; b++) len[b] = s_len[b];
    int tmax = len[0];
#pragma unroll
    for (int b = 1; b < NB; b++) tmax = (len[b] > tmax) ? len[b] : tmax;

    // ---- gold path score (all 128 threads cooperate per batch)
#pragma unroll
    for (int b = 0; b < NB; b++) {
        const int bb = b0 + b;
        float gp = 0.0f;
        for (int t = j; t < len[b]; t += 128) {
            int tg   = tags[bb * TT + t];
            float e  = feat[(bb * TT + t) * LL + tg];
            int prev = (t == 0) ? BOSL : tags[bb * TT + t - 1];
            gp += e + tr[prev * LL + tg];
        }
#pragma unroll
        for (int o = 16; o > 0; o >>= 1) gp += __shfl_down_sync(0xffffffffu, gp, o);
        if (lane == 0) s_red[b][wid] = gp;
    }
    __syncthreads();
    if (j < NB) {
        const int b = j;
        float g = s_red[b][0] + s_red[b][1] + s_red[b][2] + s_red[b][3];
        g += tr[tags[(b0 + b) * TT + len[b] - 1] * LL + EOSL];
        s_gold[b] = g;
    }

    // ---- forward recursion init: fv = tr[BOS,:] + feat[:,0,:]
    const float trb = tr[BOSL * LL + j];
    float fv[NB], c[NB], ftc[NB], ftn[NB];
#pragma unroll
    for (int b = 0; b < NB; b++) fv[b] = trb + feat[((b0 + b) * TT) * LL + j];
    if (j == 64) {
#pragma unroll
        for (int b = 0; b < NB; b++) c_sh[0][b] = fv[b];
    }
    __syncthreads();
#pragma unroll
    for (int b = 0; b < NB; b++) c[b] = c_sh[0][b];

    // depth-2 emission pipeline (len >= 256 always, so t=1,2 valid)
#pragma unroll
    for (int b = 0; b < NB; b++) {
        ftc[b] = __ldcs(&feat[((b0 + b) * TT + 1) * LL + j]);
        ftn[b] = __ldcs(&feat[((b0 + b) * TT + 2) * LL + j]);
    }

    int p = 0;
    for (int t = 1; t < tmax; t++) {
        // phase A: publish u = exp(fv - c) and next normalizer (fv[64])
#pragma unroll
        for (int b = 0; b < NB; b++) {
            u_sh[p][b][j] = __expf(fv[b] - c[b]);
        }
        if (j == 64) {
#pragma unroll
            for (int b = 0; b < NB; b++) c_sh[p][b] = fv[b];
        }
        __syncthreads();
        float nc[NB];
#pragma unroll
        for (int b = 0; b < NB; b++) nc[b] = c_sh[p][b];

        // issue prefetch for t+2 (consumed at end of step t+1)
        float fp[NB];
#pragma unroll
        for (int b = 0; b < NB; b++) fp[b] = ftn[b];
        if (t + 2 < tmax) {
#pragma unroll
            for (int b = 0; b < NB; b++)
                fp[b] = __ldcs(&feat[((b0 + b) * TT + t + 2) * LL + j]);
        }

        // phase B: v[j] = sum_i u[i] * E[i][j] for 4 batches
        const ulonglong2* U0 = (const ulonglong2*)(u_sh[p][0]);
        const ulonglong2* U1 = (const ulonglong2*)(u_sh[p][1]);
        const ulonglong2* U2 = (const ulonglong2*)(u_sh[p][2]);
        const ulonglong2* U3 = (const ulonglong2*)(u_sh[p][3]);
        ull a0 = 0, a1 = 0, a2 = 0, a3 = 0;   // batch 0
        ull d0 = 0, d1 = 0, d2 = 0, d3 = 0;   // batch 1
        ull e0 = 0, e1 = 0, e2 = 0, e3 = 0;   // batch 2
        ull f0 = 0, f1 = 0, f2 = 0, f3 = 0;   // batch 3
#pragma unroll
        for (int q = 0; q < 16; q++) {
            ulonglong2 xa = U0[2 * q];
            ulonglong2 xb = U0[2 * q + 1];
            ulonglong2 ya = U1[2 * q];
            ulonglong2 yb = U1[2 * q + 1];
            ulonglong2 za = U2[2 * q];
            ulonglong2 zb = U2[2 * q + 1];
            ulonglong2 wa = U3[2 * q];
            ulonglong2 wb = U3[2 * q + 1];
            FMA2(a0, xa.x, E2[4 * q],     a0);
            FMA2(d0, ya.x, E2[4 * q],     d0);
            FMA2(e0, za.x, E2[4 * q],     e0);
            FMA2(f0, wa.x, E2[4 * q],     f0);
            FMA2(a1, xa.y, E2[4 * q + 1], a1);
            FMA2(d1, ya.y, E2[4 * q + 1], d1);
            FMA2(e1, za.y, E2[4 * q + 1], e1);
            FMA2(f1, wa.y, E2[4 * q + 1], f1);
            FMA2(a2, xb.x, E2[4 * q + 2], a2);
            FMA2(d2, yb.x, E2[4 * q + 2], d2);
            FMA2(e2, zb.x, E2[4 * q + 2], e2);
            FMA2(f2, wb.x, E2[4 * q + 2], f2);
            FMA2(a3, xb.y, E2[4 * q + 3], a3);
            FMA2(d3, yb.y, E2[4 * q + 3], d3);
            FMA2(e3, zb.y, E2[4 * q + 3], e3);
            FMA2(f3, wb.y, E2[4 * q + 3], f3);
        }
        ADD2(a0, a0, a2); ADD2(a1, a1, a3); ADD2(a0, a0, a1);
        ADD2(d0, d0, d2); ADD2(d1, d1, d3); ADD2(d0, d0, d1);
        ADD2(e0, e0, e2); ADD2(e1, e1, e3); ADD2(e0, e0, e1);
        ADD2(f0, f0, f2); ADD2(f1, f1, f3); ADD2(f0, f0, f1);
        float s[NB], lo, hi;
        unpack2(lo, hi, a0); s[0] = lo + hi;
        unpack2(lo, hi, d0); s[1] = lo + hi;
        unpack2(lo, hi, e0); s[2] = lo + hi;
        unpack2(lo, hi, f0); s[3] = lo + hi;

#pragma unroll
        for (int b = 0; b < NB; b++) {
            if (t < len[b]) fv[b] = ftc[b] + c[b] + __logf(s[b]);
            c[b] = nc[b];
            ftc[b] = ftn[b];
            ftn[b] = fp[b];
        }
        p ^= 1;
    }

    // ---- logZ = logsumexp_j(fv[j] + tr[j][EOS]); result = logZ - gold
    {
        float te = tr[j * LL + EOSL];
        float ev[NB];
#pragma unroll
        for (int b = 0; b < NB; b++) {
            ev[b] = __expf((fv[b] + te) - c[b]);
#pragma unroll
            for (int o = 16; o > 0; o >>= 1)
                ev[b] += __shfl_down_sync(0xffffffffu, ev[b], o);
        }
        __syncthreads();
        if (lane == 0) {
#pragma unroll
            for (int b = 0; b < NB; b++) s_red[b][wid] = ev[b];
        }
        __syncthreads();
        if (j < NB) {
            const int b = j;
            float z = s_red[b][0] + s_red[b][1] + s_red[b][2] + s_red[b][3];
            g_res[b0 + b] = (c[b] + __logf(z)) - s_gold[b];
        }
    }
}

// deterministic fixed-order mean over the 512 per-batch results
__global__ void crf_reduce(float* __restrict__ out) {
    __shared__ float s[BB];
    int t = threadIdx.x;
    s[t] = g_res[t];
    __syncthreads();
#pragma unroll
    for (int k = BB / 2; k > 0; k >>= 1) {
        if (t < k) s[t] += s[t + k];
        __syncthreads();
    }
    if (t == 0) out[0] = s[0] * (1.0f / (float)BB);
}

extern "C" void kernel_launch(void* const* d_in, const int* in_sizes, int n_in,
                              void* d_out, int out_size) {
    const float* feat = (const float*)d_in[0];
    const int*   tags = (const int*)d_in[1];
    const int*   mask = (const int*)d_in[2];
    const float* tr   = (const float*)d_in[3];

    crf_fwd<<<BB / NB, 128>>>(feat, tags, mask, tr);
    crf_reduce<<<1, BB>>>((float*)d_out);
}

// round 13
// speedup vs baseline: 1.4270x; 1.4270x over previous
#include <cuda_runtime.h>
#include <cuda_bf16.h>

#define BB 512
#define TT 512
#define LL 128
#define PADL 0
#define BOSL 1
#define EOSL 2

typedef unsigned long long ull;

// per-batch (logZ - gold); reduced by second kernel
__device__ float g_res[BB];

#define FMA2(d, a, b, c) \
    asm("fma.rn.f32x2 %0, %1, %2, %3;" : "=l"(d) : "l"(a), "l"(b), "l"(c))
#define ADD2(d, a, b) \
    asm("add.rn.f32x2 %0, %1, %2;" : "=l"(d) : "l"(a), "l"(b))

__device__ __forceinline__ ull pack2(float lo, float hi) {
    ull r;
    asm("mov.b64 %0, {%1, %2};" : "=l"(r) : "f"(lo), "f"(hi));
    return r;
}
__device__ __forceinline__ void unpack2(float& lo, float& hi, ull v) {
    asm("mov.b64 {%0, %1}, %2;" : "=f"(lo), "=f"(hi) : "l"(v));
}

__global__ __launch_bounds__(128, 2) void crf_fwd(
    const float* __restrict__ feat,   // [B, T, L] f32
    const int* __restrict__ tags,     // [B, T] i32
    const int* __restrict__ mask,     // [B, T] i32 (bool widened)
    const float* __restrict__ tr)     // [L, L] f32
{
    const int j    = threadIdx.x;   // label column 0..127
    const int b0   = blockIdx.x * 2;
    const int b1   = b0 + 1;
    const int lane = j & 31;
    const int wid  = j >> 5;

    __shared__ __align__(16) float u_sh[2][2][LL];  // [buf][batch][i] : w vectors
    __shared__ float c_sh[2][2];                    // [buf][batch] : published s_ref
    __shared__ float ci_sh[2];                      // init normalizer
    __shared__ int   s_len[2];
    __shared__ float s_red[2][4];
    __shared__ float s_gold[2];

    // ---- E column j packed: E2[m] = (exp(tr[2m][j]), exp(tr[2m+1][j]))
    ull E2[64];
#pragma unroll
    for (int m = 0; m < 64; m++) {
        float lo = __expf(tr[(2 * m)     * LL + j]);
        float hi = __expf(tr[(2 * m + 1) * LL + j]);
        E2[m] = pack2(lo, hi);
    }

    // ---- sequence lengths (mask is a monotone prefix)
    if (j < 2) s_len[j] = 0;
    __syncthreads();
    {
        int cnt0 = 0, cnt1 = 0;
#pragma unroll
        for (int t = j; t < TT; t += 128) {
            cnt0 += (mask[b0 * TT + t] != 0) ? 1 : 0;
            cnt1 += (mask[b1 * TT + t] != 0) ? 1 : 0;
        }
        atomicAdd(&s_len[0], cnt0);
        atomicAdd(&s_len[1], cnt1);
    }
    __syncthreads();
    const int len0 = s_len[0];
    const int len1 = s_len[1];
    const int tmax = (len0 > len1) ? len0 : len1;

    // ---- gold path score (all 128 threads cooperate per batch)
    for (int b = 0; b < 2; b++) {
        const int bb = b0 + b;
        const int lb = (b == 0) ? len0 : len1;
        float gp = 0.0f;
        for (int t = j; t < lb; t += 128) {
            int tg   = tags[bb * TT + t];
            float e  = feat[(bb * TT + t) * LL + tg];
            int prev = (t == 0) ? BOSL : tags[bb * TT + t - 1];
            gp += e + tr[prev * LL + tg];
        }
#pragma unroll
        for (int o = 16; o > 0; o >>= 1) gp += __shfl_down_sync(0xffffffffu, gp, o);
        if (lane == 0) s_red[b][wid] = gp;
    }
    __syncthreads();
    if (j == 0) {
#pragma unroll
        for (int b = 0; b < 2; b++) {
            const int bb = b0 + b;
            const int lb = (b == 0) ? len0 : len1;
            float g = s_red[b][0] + s_red[b][1] + s_red[b][2] + s_red[b][3];
            g += tr[tags[bb * TT + lb - 1] * LL + EOSL];
            s_gold[b] = g;
        }
    }

    // ---- init: fv = tr[BOS,:] + feat[:,0,:]; w = exp(fv - fv[64])
    const float trb = tr[BOSL * LL + j];
    float fv0 = trb + feat[(b0 * TT) * LL + j];
    float fv1 = trb + feat[(b1 * TT) * LL + j];
    if (j == 64) { ci_sh[0] = fv0; ci_sh[1] = fv1; }
    __syncthreads();
    const float cinit0 = ci_sh[0];
    const float cinit1 = ci_sh[1];

    float w0 = __expf(fv0 - cinit0);
    float w1 = __expf(fv1 - cinit1);
    float spub0 = 1.0f, spub1 = 1.0f;   // published reference sums (k=0 first step)
    int   kacc0 = 0,    kacc1 = 0;      // accumulated power-of-2 log offset (uniform)

    // depth-2 emission pipeline (len >= 256 always, so t=1,2 valid)
    float ftc0 = __ldcs(&feat[(b0 * TT + 1) * LL + j]);
    float ftc1 = __ldcs(&feat[(b1 * TT + 1) * LL + j]);
    float ftn0 = __ldcs(&feat[(b0 * TT + 2) * LL + j]);
    float ftn1 = __ldcs(&feat[(b1 * TT + 2) * LL + j]);

    __syncthreads();   // protect ci_sh/c_sh reads before loop-top writes

    int p = 0;
    for (int t = 1; t < tmax; t++) {
        // publish w and reference sums
        u_sh[p][0][j] = w0;
        u_sh[p][1][j] = w1;
        if (j == 64) { c_sh[p][0] = spub0; c_sh[p][1] = spub1; }
        __syncthreads();

        // exact power-of-2 rescale factors from previous step's reference sums (ALU only)
        float sc0 = c_sh[p][0];
        float sc1 = c_sh[p][1];
        int k0 = ((__float_as_int(sc0) >> 23) & 0xff) - 127;
        int k1 = ((__float_as_int(sc1) >> 23) & 0xff) - 127;
        float scale0 = __int_as_float((127 - k0) << 23);   // 2^-k0 (exact)
        float scale1 = __int_as_float((127 - k1) << 23);   // 2^-k1 (exact)

        // off-chain: emission exps for this step + prefetch t+2
        float F0 = __expf(ftc0);
        float F1 = __expf(ftc1);
        float fp0 = ftn0, fp1 = ftn1;
        if (t + 2 < tmax) {
            fp0 = __ldcs(&feat[(b0 * TT + t + 2) * LL + j]);
            fp1 = __ldcs(&feat[(b1 * TT + t + 2) * LL + j]);
        }

        // burst: s[j] = sum_i w[i] * E[i][j]  (E packed in regs, w via LDS.128 broadcast)
        const ulonglong2* U0 = (const ulonglong2*)(u_sh[p][0]);
        const ulonglong2* U1 = (const ulonglong2*)(u_sh[p][1]);
        ull a0 = 0, a1 = 0, a2 = 0, a3 = 0;   // batch 0
        ull d0 = 0, d1 = 0, d2 = 0, d3 = 0;   // batch 1
#pragma unroll
        for (int q = 0; q < 16; q++) {
            ulonglong2 xa = U0[2 * q];
            ulonglong2 xb = U0[2 * q + 1];
            ulonglong2 ya = U1[2 * q];
            ulonglong2 yb = U1[2 * q + 1];
            FMA2(a0, xa.x, E2[4 * q],     a0);
            FMA2(d0, ya.x, E2[4 * q],     d0);
            FMA2(a1, xa.y, E2[4 * q + 1], a1);
            FMA2(d1, ya.y, E2[4 * q + 1], d1);
            FMA2(a2, xb.x, E2[4 * q + 2], a2);
            FMA2(d2, yb.x, E2[4 * q + 2], d2);
            FMA2(a3, xb.y, E2[4 * q + 3], a3);
            FMA2(d3, yb.y, E2[4 * q + 3], d3);
        }
        ADD2(a0, a0, a2);
        ADD2(a1, a1, a3);
        ADD2(a0, a0, a1);
        ADD2(d0, d0, d2);
        ADD2(d1, d1, d3);
        ADD2(d0, d0, d1);
        float slo, shi, tlo, thi;
        unpack2(slo, shi, a0);
        unpack2(tlo, thi, d0);
        float s0 = slo + shi;
        float s1 = tlo + thi;

        // linear-domain update (no transcendentals on the chain)
        if (t < len0) { w0 = s0 * F0 * scale0; kacc0 += k0; spub0 = s0; }
        if (t < len1) { w1 = s1 * F1 * scale1; kacc1 += k1; spub1 = s1; }
        ftc0 = ftn0; ftc1 = ftn1;
        ftn0 = fp0;  ftn1 = fp1;
        p ^= 1;
    }

    // ---- logZ = cinit + kacc*ln2 + log( sum_j w[j] * exp(tr[j][EOS]) )
    {
        float te = __expf(tr[j * LL + EOSL]);
        float e0 = w0 * te;
        float e1 = w1 * te;
#pragma unroll
        for (int o = 16; o > 0; o >>= 1) {
            e0 += __shfl_down_sync(0xffffffffu, e0, o);
            e1 += __shfl_down_sync(0xffffffffu, e1, o);
        }
        __syncthreads();
        if (lane == 0) { s_red[0][wid] = e0; s_red[1][wid] = e1; }
        __syncthreads();
        if (j == 0) {
            float z0 = s_red[0][0] + s_red[0][1] + s_red[0][2] + s_red[0][3];
            float z1 = s_red[1][0] + s_red[1][1] + s_red[1][2] + s_red[1][3];
            double logZ0 = (double)cinit0 + (double)kacc0 * 0.6931471805599453
                         + (double)__logf(z0);
            double logZ1 = (double)cinit1 + (double)kacc1 * 0.6931471805599453
                         + (double)__logf(z1);
            g_res[b0] = (float)(logZ0 - (double)s_gold[0]);
            g_res[b1] = (float)(logZ1 - (double)s_gold[1]);
        }
    }
}

// deterministic fixed-order mean over the 512 per-batch results
__global__ void crf_reduce(float* __restrict__ out) {
    __shared__ float s[BB];
    int t = threadIdx.x;
    s[t] = g_res[t];
    __syncthreads();
#pragma unroll
    for (int k = BB / 2; k > 0; k >>= 1) {
        if (t < k) s[t] += s[t + k];
        __syncthreads();
    }
    if (t == 0) out[0] = s[0] * (1.0f / (float)BB);
}

extern "C" void kernel_launch(void* const* d_in, const int* in_sizes, int n_in,
                              void* d_out, int out_size) {
    const float* feat = (const float*)d_in[0];
    const int*   tags = (const int*)d_in[1];
    const int*   mask = (const int*)d_in[2];
    const float* tr   = (const float*)d_in[3];

    crf_fwd<<<BB / 2, 128>>>(feat, tags, mask, tr);
    crf_reduce<<<1, BB>>>((float*)d_out);
}

// round 14
// speedup vs baseline: 1.5415x; 1.0802x over previous
#include <cuda_runtime.h>
#include <cuda_bf16.h>

#define BB 512
#define TT 512
#define LL 128
#define PADL 0
#define BOSL 1
#define EOSL 2

typedef unsigned long long ull;

__device__ float g_res[BB];
__device__ int   g_perm[BB];   // batch ids sorted by length (ascending)
__device__ int   g_len[BB];    // length per batch id

#define FMA2(d, a, b, c) \
    asm("fma.rn.f32x2 %0, %1, %2, %3;" : "=l"(d) : "l"(a), "l"(b), "l"(c))
#define ADD2(d, a, b) \
    asm("add.rn.f32x2 %0, %1, %2;" : "=l"(d) : "l"(a), "l"(b))

__device__ __forceinline__ ull pack2(float lo, float hi) {
    ull r;
    asm("mov.b64 %0, {%1, %2};" : "=l"(r) : "f"(lo), "f"(hi));
    return r;
}
__device__ __forceinline__ void unpack2(float& lo, float& hi, ull v) {
    asm("mov.b64 {%0, %1}, %2;" : "=f"(lo), "=f"(hi) : "l"(v));
}

// ---- prep: lengths + bitonic sort by length (1 CTA, 512 threads) ----
__global__ void crf_prep(const int* __restrict__ mask) {
    __shared__ int sk[BB];
    __shared__ int sv[BB];
    const int t    = threadIdx.x;
    const int w    = t >> 5;
    const int lane = t & 31;

    // warp w counts batches w, w+16, ... (coalesced across lanes)
    for (int b = w; b < BB; b += 16) {
        int cnt = 0;
        for (int q = lane; q < TT; q += 32) cnt += (mask[b * TT + q] != 0) ? 1 : 0;
#pragma unroll
        for (int o = 16; o > 0; o >>= 1) cnt += __shfl_down_sync(0xffffffffu, cnt, o);
        if (lane == 0) sk[b] = cnt;
    }
    __syncthreads();
    g_len[t] = sk[t];
    sv[t] = t;
    __syncthreads();

    // bitonic sort ascending by sk
    for (int k = 2; k <= BB; k <<= 1) {
        for (int jj = k >> 1; jj > 0; jj >>= 1) {
            int ixj = t ^ jj;
            if (ixj > t) {
                bool dir = ((t & k) == 0);
                if ((sk[t] > sk[ixj]) == dir) {
                    int tk = sk[t]; sk[t] = sk[ixj]; sk[ixj] = tk;
                    int tv = sv[t]; sv[t] = sv[ixj]; sv[ixj] = tv;
                }
            }
            __syncthreads();
        }
    }
    g_perm[t] = sv[t];
}

// ---- forward: CTA x handles (rank x, rank 511-x) => lenA <= lenB, lenA+lenB ~ const
__global__ __launch_bounds__(128, 2) void crf_fwd(
    const float* __restrict__ feat,   // [B, T, L] f32
    const int* __restrict__ tags,     // [B, T] i32
    const float* __restrict__ tr)     // [L, L] f32
{
    const int j    = threadIdx.x;   // label column 0..127
    const int x    = blockIdx.x;
    const int lane = j & 31;
    const int wid  = j >> 5;

    __shared__ __align__(16) float u_sh[2][2][LL];  // [buf][slot A/B][i]
    __shared__ float c_sh[2][2];
    __shared__ float s_red[2][4];
    __shared__ float s_gold[2];
    __shared__ int   s_bid[2];

    if (j == 0) s_bid[0] = g_perm[x];
    if (j == 1) s_bid[1] = g_perm[BB - 1 - x];
    __syncthreads();
    const int bA = s_bid[0];
    const int bB = s_bid[1];
    const int lenA = g_len[bA];
    const int lenB = g_len[bB];

    // ---- E column j packed: E2[m] = (exp(tr[2m][j]), exp(tr[2m+1][j]))
    ull E2[64];
#pragma unroll
    for (int m = 0; m < 64; m++) {
        float lo = __expf(tr[(2 * m)     * LL + j]);
        float hi = __expf(tr[(2 * m + 1) * LL + j]);
        E2[m] = pack2(lo, hi);
    }

    // ---- gold path scores
    for (int sb = 0; sb < 2; sb++) {
        const int bb = (sb == 0) ? bA : bB;
        const int lb = (sb == 0) ? lenA : lenB;
        float gp = 0.0f;
        for (int t = j; t < lb; t += 128) {
            int tg   = tags[bb * TT + t];
            float e  = feat[(bb * TT + t) * LL + tg];
            int prev = (t == 0) ? BOSL : tags[bb * TT + t - 1];
            gp += e + tr[prev * LL + tg];
        }
#pragma unroll
        for (int o = 16; o > 0; o >>= 1) gp += __shfl_down_sync(0xffffffffu, gp, o);
        if (lane == 0) s_red[sb][wid] = gp;
    }
    __syncthreads();
    if (j < 2) {
        const int sb = j;
        const int bb = (sb == 0) ? bA : bB;
        const int lb = (sb == 0) ? lenA : lenB;
        float g = s_red[sb][0] + s_red[sb][1] + s_red[sb][2] + s_red[sb][3];
        g += tr[tags[bb * TT + lb - 1] * LL + EOSL];
        s_gold[sb] = g;
    }

    // ---- init: fv = tr[BOS,:] + feat[:,0,:]
    const float trb = tr[BOSL * LL + j];
    float fvA = trb + feat[(bA * TT) * LL + j];
    float fvB = trb + feat[(bB * TT) * LL + j];
    if (j == 64) { c_sh[0][0] = fvA; c_sh[0][1] = fvB; }
    __syncthreads();
    float cA = c_sh[0][0];
    float cB = c_sh[0][1];

    float ftA = __ldcs(&feat[(bA * TT + 1) * LL + j]);  // len >= 256 always
    float ftB = __ldcs(&feat[(bB * TT + 1) * LL + j]);

    int p = 0;

    // ======== Phase 1: both batches active (t = 1 .. lenA-1) ========
    for (int t = 1; t < lenA; t++) {
        float uA = __expf(fvA - cA);
        float uB = __expf(fvB - cB);
        u_sh[p][0][j] = uA;
        u_sh[p][1][j] = uB;
        if (j == 64) { c_sh[p][0] = fvA; c_sh[p][1] = fvB; }
        __syncthreads();
        float ncA = c_sh[p][0];
        float ncB = c_sh[p][1];

        float nftA = (t + 1 < lenA) ? __ldcs(&feat[(bA * TT + t + 1) * LL + j]) : 0.0f;
        float nftB = (t + 1 < lenB) ? __ldcs(&feat[(bB * TT + t + 1) * LL + j]) : 0.0f;

        const ulonglong2* U0 = (const ulonglong2*)(u_sh[p][0]);
        const ulonglong2* U1 = (const ulonglong2*)(u_sh[p][1]);
        ull a0 = 0, a1 = 0, a2 = 0, a3 = 0;
        ull d0 = 0, d1 = 0, d2 = 0, d3 = 0;
#pragma unroll
        for (int q = 0; q < 16; q++) {
            ulonglong2 xa = U0[2 * q];
            ulonglong2 xb = U0[2 * q + 1];
            ulonglong2 ya = U1[2 * q];
            ulonglong2 yb = U1[2 * q + 1];
            FMA2(a0, xa.x, E2[4 * q],     a0);
            FMA2(d0, ya.x, E2[4 * q],     d0);
            FMA2(a1, xa.y, E2[4 * q + 1], a1);
            FMA2(d1, ya.y, E2[4 * q + 1], d1);
            FMA2(a2, xb.x, E2[4 * q + 2], a2);
            FMA2(d2, yb.x, E2[4 * q + 2], d2);
            FMA2(a3, xb.y, E2[4 * q + 3], a3);
            FMA2(d3, yb.y, E2[4 * q + 3], d3);
        }
        ADD2(a0, a0, a2); ADD2(a1, a1, a3); ADD2(a0, a0, a1);
        ADD2(d0, d0, d2); ADD2(d1, d1, d3); ADD2(d0, d0, d1);
        float slo, shi, tlo, thi;
        unpack2(slo, shi, a0);
        unpack2(tlo, thi, d0);

        fvA = ftA + cA + __logf(slo + shi);
        fvB = ftB + cB + __logf(tlo + thi);
        cA = ncA; cB = ncB;
        ftA = nftA; ftB = nftB;
        p ^= 1;
    }

    // ======== Phase 2: only batch B (t = lenA .. lenB-1), half-cost steps ========
    for (int t = lenA; t < lenB; t++) {
        float uB = __expf(fvB - cB);
        u_sh[p][1][j] = uB;
        if (j == 64) c_sh[p][1] = fvB;
        __syncthreads();
        float ncB = c_sh[p][1];

        float nftB = (t + 1 < lenB) ? __ldcs(&feat[(bB * TT + t + 1) * LL + j]) : 0.0f;

        const ulonglong2* U1 = (const ulonglong2*)(u_sh[p][1]);
        ull d0 = 0, d1 = 0, d2 = 0, d3 = 0;
#pragma unroll
        for (int q = 0; q < 16; q++) {
            ulonglong2 ya = U1[2 * q];
            ulonglong2 yb = U1[2 * q + 1];
            FMA2(d0, ya.x, E2[4 * q],     d0);
            FMA2(d1, ya.y, E2[4 * q + 1], d1);
            FMA2(d2, yb.x, E2[4 * q + 2], d2);
            FMA2(d3, yb.y, E2[4 * q + 3], d3);
        }
        ADD2(d0, d0, d2); ADD2(d1, d1, d3); ADD2(d0, d0, d1);
        float tlo, thi;
        unpack2(tlo, thi, d0);

        fvB = ftB + cB + __logf(tlo + thi);
        cB = ncB;
        ftB = nftB;
        p ^= 1;
    }

    // ---- logZ = logsumexp_j(fv[j] + tr[j][EOS]); result = logZ - gold
    {
        float te = tr[j * LL + EOSL];
        float eA = __expf((fvA + te) - cA);
        float eB = __expf((fvB + te) - cB);
#pragma unroll
        for (int o = 16; o > 0; o >>= 1) {
            eA += __shfl_down_sync(0xffffffffu, eA, o);
            eB += __shfl_down_sync(0xffffffffu, eB, o);
        }
        __syncthreads();
        if (lane == 0) { s_red[0][wid] = eA; s_red[1][wid] = eB; }
        __syncthreads();
        if (j == 0) {
            float zA = s_red[0][0] + s_red[0][1] + s_red[0][2] + s_red[0][3];
            float zB = s_red[1][0] + s_red[1][1] + s_red[1][2] + s_red[1][3];
            g_res[bA] = (cA + __logf(zA)) - s_gold[0];
            g_res[bB] = (cB + __logf(zB)) - s_gold[1];
        }
    }
}

// deterministic fixed-order mean over the 512 per-batch results
__global__ void crf_reduce(float* __restrict__ out) {
    __shared__ float s[BB];
    int t = threadIdx.x;
    s[t] = g_res[t];
    __syncthreads();
#pragma unroll
    for (int k = BB / 2; k > 0; k >>= 1) {
        if (t < k) s[t] += s[t + k];
        __syncthreads();
    }
    if (t == 0) out[0] = s[0] * (1.0f / (float)BB);
}

extern "C" void kernel_launch(void* const* d_in, const int* in_sizes, int n_in,
                              void* d_out, int out_size) {
    const float* feat = (const float*)d_in[0];
    const int*   tags = (const int*)d_in[1];
    const int*   mask = (const int*)d_in[2];
    const float* tr   = (const float*)d_in[3];

    crf_prep<<<1, BB>>>(mask);
    crf_fwd<<<BB / 2, 128>>>(feat, tags, tr);
    crf_reduce<<<1, BB>>>((float*)d_out);
}

// round 15
// speedup vs baseline: 1.5841x; 1.0277x over previous
#include <cuda_runtime.h>
#include <cuda_bf16.h>

#define BB 512
#define TT 512
#define LL 128
#define PADL 0
#define BOSL 1
#define EOSL 2

typedef unsigned long long ull;

__device__ float g_res[BB];
__device__ int   g_perm[BB];   // batch ids sorted by length (ascending)
__device__ int   g_len[BB];    // length per batch id

#define FMA2(d, a, b, c) \
    asm("fma.rn.f32x2 %0, %1, %2, %3;" : "=l"(d) : "l"(a), "l"(b), "l"(c))
#define ADD2(d, a, b) \
    asm("add.rn.f32x2 %0, %1, %2;" : "=l"(d) : "l"(a), "l"(b))

__device__ __forceinline__ ull pack2(float lo, float hi) {
    ull r;
    asm("mov.b64 %0, {%1, %2};" : "=l"(r) : "f"(lo), "f"(hi));
    return r;
}
__device__ __forceinline__ void unpack2(float& lo, float& hi, ull v) {
    asm("mov.b64 {%0, %1}, %2;" : "=f"(lo), "=f"(hi) : "l"(v));
}

// ---- prep 1: parallel length count (one CTA per batch) ----
__global__ void crf_count(const int* __restrict__ mask) {
    const int b    = blockIdx.x;
    const int t    = threadIdx.x;
    const int lane = t & 31;
    const int wid  = t >> 5;
    __shared__ int sred[4];

    int cnt = 0;
#pragma unroll
    for (int q = t; q < TT; q += 128) cnt += (mask[b * TT + q] != 0) ? 1 : 0;
#pragma unroll
    for (int o = 16; o > 0; o >>= 1) cnt += __shfl_down_sync(0xffffffffu, cnt, o);
    if (lane == 0) sred[wid] = cnt;
    __syncthreads();
    if (t == 0) g_len[b] = sred[0] + sred[1] + sred[2] + sred[3];
}

// ---- prep 2: bitonic sort of 512 (len, id) pairs (1 CTA) ----
__global__ void crf_sort() {
    __shared__ int sk[BB];
    __shared__ int sv[BB];
    const int t = threadIdx.x;
    sk[t] = g_len[t];
    sv[t] = t;
    __syncthreads();
    for (int k = 2; k <= BB; k <<= 1) {
        for (int jj = k >> 1; jj > 0; jj >>= 1) {
            int ixj = t ^ jj;
            if (ixj > t) {
                bool dir = ((t & k) == 0);
                if ((sk[t] > sk[ixj]) == dir) {
                    int tk = sk[t]; sk[t] = sk[ixj]; sk[ixj] = tk;
                    int tv = sv[t]; sv[t] = sv[ixj]; sv[ixj] = tv;
                }
            }
            __syncthreads();
        }
    }
    g_perm[t] = sv[t];
}

// ---- forward: CTA x handles (rank x, rank 511-x) => lenA <= lenB, lenA+lenB ~ const
__global__ __launch_bounds__(128, 2) void crf_fwd(
    const float* __restrict__ feat,   // [B, T, L] f32
    const int* __restrict__ tags,     // [B, T] i32
    const float* __restrict__ tr)     // [L, L] f32
{
    const int j    = threadIdx.x;   // label column 0..127
    const int x    = blockIdx.x;
    const int lane = j & 31;
    const int wid  = j >> 5;

    __shared__ __align__(16) float u_sh[2][2][LL];  // [buf][slot A/B][i]
    __shared__ float c_sh[2][2];
    __shared__ float s_red[2][4];
    __shared__ float s_gold[2];
    __shared__ int   s_bid[2];

    if (j == 0) s_bid[0] = g_perm[x];
    if (j == 1) s_bid[1] = g_perm[BB - 1 - x];
    __syncthreads();
    const int bA = s_bid[0];
    const int bB = s_bid[1];
    const int lenA = g_len[bA];
    const int lenB = g_len[bB];

    // ---- E column j packed: E2[m] = (exp(tr[2m][j]), exp(tr[2m+1][j]))
    ull E2[64];
#pragma unroll
    for (int m = 0; m < 64; m++) {
        float lo = __expf(tr[(2 * m)     * LL + j]);
        float hi = __expf(tr[(2 * m + 1) * LL + j]);
        E2[m] = pack2(lo, hi);
    }

    // ---- gold path scores
    for (int sb = 0; sb < 2; sb++) {
        const int bb = (sb == 0) ? bA : bB;
        const int lb = (sb == 0) ? lenA : lenB;
        float gp = 0.0f;
        for (int t = j; t < lb; t += 128) {
            int tg   = tags[bb * TT + t];
            float e  = feat[(bb * TT + t) * LL + tg];
            int prev = (t == 0) ? BOSL : tags[bb * TT + t - 1];
            gp += e + tr[prev * LL + tg];
        }
#pragma unroll
        for (int o = 16; o > 0; o >>= 1) gp += __shfl_down_sync(0xffffffffu, gp, o);
        if (lane == 0) s_red[sb][wid] = gp;
    }
    __syncthreads();
    if (j < 2) {
        const int sb = j;
        const int bb = (sb == 0) ? bA : bB;
        const int lb = (sb == 0) ? lenA : lenB;
        float g = s_red[sb][0] + s_red[sb][1] + s_red[sb][2] + s_red[sb][3];
        g += tr[tags[bb * TT + lb - 1] * LL + EOSL];
        s_gold[sb] = g;
    }

    // ---- init: fv = tr[BOS,:] + feat[:,0,:]
    const float trb = tr[BOSL * LL + j];
    float fvA = trb + feat[(bA * TT) * LL + j];
    float fvB = trb + feat[(bB * TT) * LL + j];
    if (j == 64) { c_sh[0][0] = fvA; c_sh[0][1] = fvB; }
    __syncthreads();
    float cA = c_sh[0][0];
    float cB = c_sh[0][1];

    float ftA = __ldcs(&feat[(bA * TT + 1) * LL + j]);  // len >= 256 always
    float ftB = __ldcs(&feat[(bB * TT + 1) * LL + j]);

    int p = 0;

    // ======== Phase 1: both batches active (t = 1 .. lenA-1) ========
    for (int t = 1; t < lenA; t++) {
        float uA = __expf(fvA - cA);
        float uB = __expf(fvB - cB);
        u_sh[p][0][j] = uA;
        u_sh[p][1][j] = uB;
        if (j == 64) { c_sh[p][0] = fvA; c_sh[p][1] = fvB; }
        __syncthreads();
        float ncA = c_sh[p][0];
        float ncB = c_sh[p][1];

        float nftA = (t + 1 < lenA) ? __ldcs(&feat[(bA * TT + t + 1) * LL + j]) : 0.0f;
        float nftB = (t + 1 < lenB) ? __ldcs(&feat[(bB * TT + t + 1) * LL + j]) : 0.0f;

        const ulonglong2* U0 = (const ulonglong2*)(u_sh[p][0]);
        const ulonglong2* U1 = (const ulonglong2*)(u_sh[p][1]);
        ull a0 = 0, a1 = 0, a2 = 0, a3 = 0;
        ull d0 = 0, d1 = 0, d2 = 0, d3 = 0;
#pragma unroll
        for (int q = 0; q < 16; q++) {
            ulonglong2 xa = U0[2 * q];
            ulonglong2 xb = U0[2 * q + 1];
            ulonglong2 ya = U1[2 * q];
            ulonglong2 yb = U1[2 * q + 1];
            FMA2(a0, xa.x, E2[4 * q],     a0);
            FMA2(d0, ya.x, E2[4 * q],     d0);
            FMA2(a1, xa.y, E2[4 * q + 1], a1);
            FMA2(d1, ya.y, E2[4 * q + 1], d1);
            FMA2(a2, xb.x, E2[4 * q + 2], a2);
            FMA2(d2, yb.x, E2[4 * q + 2], d2);
            FMA2(a3, xb.y, E2[4 * q + 3], a3);
            FMA2(d3, yb.y, E2[4 * q + 3], d3);
        }
        ADD2(a0, a0, a2); ADD2(a1, a1, a3); ADD2(a0, a0, a1);
        ADD2(d0, d0, d2); ADD2(d1, d1, d3); ADD2(d0, d0, d1);
        float slo, shi, tlo, thi;
        unpack2(slo, shi, a0);
        unpack2(tlo, thi, d0);

        fvA = ftA + cA + __logf(slo + shi);
        fvB = ftB + cB + __logf(tlo + thi);
        cA = ncA; cB = ncB;
        ftA = nftA; ftB = nftB;
        p ^= 1;
    }

    // ======== Phase 2: only batch B (t = lenA .. lenB-1), half-cost steps ========
    for (int t = lenA; t < lenB; t++) {
        float uB = __expf(fvB - cB);
        u_sh[p][1][j] = uB;
        if (j == 64) c_sh[p][1] = fvB;
        __syncthreads();
        float ncB = c_sh[p][1];

        float nftB = (t + 1 < lenB) ? __ldcs(&feat[(bB * TT + t + 1) * LL + j]) : 0.0f;

        const ulonglong2* U1 = (const ulonglong2*)(u_sh[p][1]);
        ull d0 = 0, d1 = 0, d2 = 0, d3 = 0;
#pragma unroll
        for (int q = 0; q < 16; q++) {
            ulonglong2 ya = U1[2 * q];
            ulonglong2 yb = U1[2 * q + 1];
            FMA2(d0, ya.x, E2[4 * q],     d0);
            FMA2(d1, ya.y, E2[4 * q + 1], d1);
            FMA2(d2, yb.x, E2[4 * q + 2], d2);
            FMA2(d3, yb.y, E2[4 * q + 3], d3);
        }
        ADD2(d0, d0, d2); ADD2(d1, d1, d3); ADD2(d0, d0, d1);
        float tlo, thi;
        unpack2(tlo, thi, d0);

        fvB = ftB + cB + __logf(tlo + thi);
        cB = ncB;
        ftB = nftB;
        p ^= 1;
    }

    // ---- logZ = logsumexp_j(fv[j] + tr[j][EOS]); result = logZ - gold
    {
        float te = tr[j * LL + EOSL];
        float eA = __expf((fvA + te) - cA);
        float eB = __expf((fvB + te) - cB);
#pragma unroll
        for (int o = 16; o > 0; o >>= 1) {
            eA += __shfl_down_sync(0xffffffffu, eA, o);
            eB += __shfl_down_sync(0xffffffffu, eB, o);
        }
        __syncthreads();
        if (lane == 0) { s_red[0][wid] = eA; s_red[1][wid] = eB; }
        __syncthreads();
        if (j == 0) {
            float zA = s_red[0][0] + s_red[0][1] + s_red[0][2] + s_red[0][3];
            float zB = s_red[1][0] + s_red[1][1] + s_red[1][2] + s_red[1][3];
            g_res[bA] = (cA + __logf(zA)) - s_gold[0];
            g_res[bB] = (cB + __logf(zB)) - s_gold[1];
        }
    }
}

// deterministic fixed-order mean: shfl-tree (512 = 16 warps -> 16 partials -> warp 0)
__global__ void crf_reduce(float* __restrict__ out) {
    __shared__ float sred[16];
    const int t    = threadIdx.x;
    const int lane = t & 31;
    const int wid  = t >> 5;

    float v = g_res[t];
#pragma unroll
    for (int o = 16; o > 0; o >>= 1) v += __shfl_down_sync(0xffffffffu, v, o);
    if (lane == 0) sred[wid] = v;
    __syncthreads();
    if (wid == 0) {
        float w = (lane < 16) ? sred[lane] : 0.0f;
#pragma unroll
        for (int o = 8; o > 0; o >>= 1) w += __shfl_down_sync(0xffffffffu, w, o);
        if (lane == 0) out[0] = w * (1.0f / (float)BB);
    }
}

extern "C" void kernel_launch(void* const* d_in, const int* in_sizes, int n_in,
                              void* d_out, int out_size) {
    const float* feat = (const float*)d_in[0];
    const int*   tags = (const int*)d_in[1];
    const int*   mask = (const int*)d_in[2];
    const float* tr   = (const float*)d_in[3];

    crf_count<<<BB, 128>>>(mask);
    crf_sort<<<1, BB>>>();
    crf_fwd<<<BB / 2, 128>>>(feat, tags, tr);
    crf_reduce<<<1, BB>>>((float*)d_out);
}

// round 16
// speedup vs baseline: 1.7653x; 1.1143x over previous
#include <cuda_runtime.h>
#include <cuda_bf16.h>

#define BB 512
#define TT 512
#define LL 128
#define PADL 0
#define BOSL 1
#define EOSL 2

typedef unsigned long long ull;

__device__ float g_res[BB];
__device__ int   g_perm[BB];   // batch ids sorted by length (ascending)
__device__ int   g_len[BB];    // length per batch id

// ---- prep 1: parallel length count (one CTA per batch) ----
__global__ void crf_count(const int* __restrict__ mask) {
    const int b    = blockIdx.x;
    const int t    = threadIdx.x;
    const int lane = t & 31;
    const int wid  = t >> 5;
    __shared__ int sred[4];

    int cnt = 0;
#pragma unroll
    for (int q = t; q < TT; q += 128) cnt += (mask[b * TT + q] != 0) ? 1 : 0;
#pragma unroll
    for (int o = 16; o > 0; o >>= 1) cnt += __shfl_down_sync(0xffffffffu, cnt, o);
    if (lane == 0) sred[wid] = cnt;
    __syncthreads();
    if (t == 0) g_len[b] = sred[0] + sred[1] + sred[2] + sred[3];
}

// ---- prep 2: bitonic sort of 512 (len, id) pairs (1 CTA) ----
__global__ void crf_sort() {
    __shared__ int sk[BB];
    __shared__ int sv[BB];
    const int t = threadIdx.x;
    sk[t] = g_len[t];
    sv[t] = t;
    __syncthreads();
    for (int k = 2; k <= BB; k <<= 1) {
        for (int jj = k >> 1; jj > 0; jj >>= 1) {
            int ixj = t ^ jj;
            if (ixj > t) {
                bool dir = ((t & k) == 0);
                if ((sk[t] > sk[ixj]) == dir) {
                    int tk = sk[t]; sk[t] = sk[ixj]; sk[ixj] = tk;
                    int tv = sv[t]; sv[t] = sv[ixj]; sv[ixj] = tv;
                }
            }
            __syncthreads();
        }
    }
    g_perm[t] = sv[t];
}

// ---- forward: CTA x handles (rank x, rank 511-x); bf16 HFMA2 inner loop ----
__global__ __launch_bounds__(128, 2) void crf_fwd(
    const float* __restrict__ feat,   // [B, T, L] f32
    const int* __restrict__ tags,     // [B, T] i32
    const float* __restrict__ tr)     // [L, L] f32
{
    const int j    = threadIdx.x;   // label column 0..127
    const int x    = blockIdx.x;
    const int lane = j & 31;
    const int wid  = j >> 5;

    __shared__ __align__(16) __nv_bfloat16 u_sh[2][2][LL];  // [buf][slot][i]
    __shared__ float c_sh[2][2];
    __shared__ float s_red[2][4];
    __shared__ float s_gold[2];
    __shared__ int   s_bid[2];

    if (j == 0) s_bid[0] = g_perm[x];
    if (j == 1) s_bid[1] = g_perm[BB - 1 - x];
    __syncthreads();
    const int bA = s_bid[0];
    const int bB = s_bid[1];
    const int lenA = g_len[bA];
    const int lenB = g_len[bB];

    // ---- E column j as bf16x2: E2h[m] = (E[2m][j], E[2m+1][j])
    __nv_bfloat162 E2h[64];
#pragma unroll
    for (int m = 0; m < 64; m++) {
        float lo = __expf(tr[(2 * m)     * LL + j]);
        float hi = __expf(tr[(2 * m + 1) * LL + j]);
        E2h[m] = __floats2bfloat162_rn(lo, hi);
    }

    // ---- gold path scores (fp32, exact)
    for (int sb = 0; sb < 2; sb++) {
        const int bb = (sb == 0) ? bA : bB;
        const int lb = (sb == 0) ? lenA : lenB;
        float gp = 0.0f;
        for (int t = j; t < lb; t += 128) {
            int tg   = tags[bb * TT + t];
            float e  = feat[(bb * TT + t) * LL + tg];
            int prev = (t == 0) ? BOSL : tags[bb * TT + t - 1];
            gp += e + tr[prev * LL + tg];
        }
#pragma unroll
        for (int o = 16; o > 0; o >>= 1) gp += __shfl_down_sync(0xffffffffu, gp, o);
        if (lane == 0) s_red[sb][wid] = gp;
    }
    __syncthreads();
    if (j < 2) {
        const int sb = j;
        const int bb = (sb == 0) ? bA : bB;
        const int lb = (sb == 0) ? lenA : lenB;
        float g = s_red[sb][0] + s_red[sb][1] + s_red[sb][2] + s_red[sb][3];
        g += tr[tags[bb * TT + lb - 1] * LL + EOSL];
        s_gold[sb] = g;
    }

    // ---- init: fv = tr[BOS,:] + feat[:,0,:]
    const float trb = tr[BOSL * LL + j];
    float fvA = trb + feat[(bA * TT) * LL + j];
    float fvB = trb + feat[(bB * TT) * LL + j];
    if (j == 64) { c_sh[0][0] = fvA; c_sh[0][1] = fvB; }
    __syncthreads();
    float cA = c_sh[0][0];
    float cB = c_sh[0][1];

    float ftA = __ldcs(&feat[(bA * TT + 1) * LL + j]);  // len >= 256 always
    float ftB = __ldcs(&feat[(bB * TT + 1) * LL + j]);

    const __nv_bfloat162 z2 = __floats2bfloat162_rn(0.0f, 0.0f);
    int p = 0;

    // ======== Phase 1: both batches active (t = 1 .. lenA-1) ========
    for (int t = 1; t < lenA; t++) {
        float uA = __expf(fvA - cA);
        float uB = __expf(fvB - cB);
        u_sh[p][0][j] = __float2bfloat16_rn(uA);
        u_sh[p][1][j] = __float2bfloat16_rn(uB);
        if (j == 64) { c_sh[p][0] = fvA; c_sh[p][1] = fvB; }
        __syncthreads();
        float ncA = c_sh[p][0];
        float ncB = c_sh[p][1];

        float nftA = (t + 1 < lenA) ? __ldcs(&feat[(bA * TT + t + 1) * LL + j]) : 0.0f;
        float nftB = (t + 1 < lenB) ? __ldcs(&feat[(bB * TT + t + 1) * LL + j]) : 0.0f;

        const float4* U0 = (const float4*)(&u_sh[p][0][0]);
        const float4* U1 = (const float4*)(&u_sh[p][1][0]);
        __nv_bfloat162 accA[8], accB[8];
#pragma unroll
        for (int r = 0; r < 8; r++) { accA[r] = z2; accB[r] = z2; }
#pragma unroll
        for (int q = 0; q < 16; q++) {
            float4 va = U0[q];
            float4 vb = U1[q];
            const __nv_bfloat162* wa = (const __nv_bfloat162*)&va;
            const __nv_bfloat162* wb = (const __nv_bfloat162*)&vb;
#pragma unroll
            for (int r = 0; r < 4; r++) {
                int m = 4 * q + r;
                accA[m & 7] = __hfma2(wa[r], E2h[m], accA[m & 7]);
                accB[m & 7] = __hfma2(wb[r], E2h[m], accB[m & 7]);
            }
        }
        // tree combine 8 -> 1 per batch
#pragma unroll
        for (int r = 0; r < 4; r++) { accA[r] = __hadd2(accA[r], accA[r + 4]);
                                      accB[r] = __hadd2(accB[r], accB[r + 4]); }
        accA[0] = __hadd2(accA[0], accA[2]); accA[1] = __hadd2(accA[1], accA[3]);
        accB[0] = __hadd2(accB[0], accB[2]); accB[1] = __hadd2(accB[1], accB[3]);
        accA[0] = __hadd2(accA[0], accA[1]);
        accB[0] = __hadd2(accB[0], accB[1]);
        float sA = __bfloat162float(__low2bfloat16(accA[0]))
                 + __bfloat162float(__high2bfloat16(accA[0]));
        float sB = __bfloat162float(__low2bfloat16(accB[0]))
                 + __bfloat162float(__high2bfloat16(accB[0]));

        fvA = ftA + cA + __logf(sA);
        fvB = ftB + cB + __logf(sB);
        cA = ncA; cB = ncB;
        ftA = nftA; ftB = nftB;
        p ^= 1;
    }

    // ======== Phase 2: only batch B (t = lenA .. lenB-1) ========
    for (int t = lenA; t < lenB; t++) {
        float uB = __expf(fvB - cB);
        u_sh[p][1][j] = __float2bfloat16_rn(uB);
        if (j == 64) c_sh[p][1] = fvB;
        __syncthreads();
        float ncB = c_sh[p][1];

        float nftB = (t + 1 < lenB) ? __ldcs(&feat[(bB * TT + t + 1) * LL + j]) : 0.0f;

        const float4* U1 = (const float4*)(&u_sh[p][1][0]);
        __nv_bfloat162 accB[8];
#pragma unroll
        for (int r = 0; r < 8; r++) accB[r] = z2;
#pragma unroll
        for (int q = 0; q < 16; q++) {
            float4 vb = U1[q];
            const __nv_bfloat162* wb = (const __nv_bfloat162*)&vb;
#pragma unroll
            for (int r = 0; r < 4; r++) {
                int m = 4 * q + r;
                accB[m & 7] = __hfma2(wb[r], E2h[m], accB[m & 7]);
            }
        }
#pragma unroll
        for (int r = 0; r < 4; r++) accB[r] = __hadd2(accB[r], accB[r + 4]);
        accB[0] = __hadd2(accB[0], accB[2]); accB[1] = __hadd2(accB[1], accB[3]);
        accB[0] = __hadd2(accB[0], accB[1]);
        float sB = __bfloat162float(__low2bfloat16(accB[0]))
                 + __bfloat162float(__high2bfloat16(accB[0]));

        fvB = ftB + cB + __logf(sB);
        cB = ncB;
        ftB = nftB;
        p ^= 1;
    }

    // ---- logZ = logsumexp_j(fv[j] + tr[j][EOS]); result = logZ - gold (fp32)
    {
        float te = tr[j * LL + EOSL];
        float eA = __expf((fvA + te) - cA);
        float eB = __expf((fvB + te) - cB);
#pragma unroll
        for (int o = 16; o > 0; o >>= 1) {
            eA += __shfl_down_sync(0xffffffffu, eA, o);
            eB += __shfl_down_sync(0xffffffffu, eB, o);
        }
        __syncthreads();
        if (lane == 0) { s_red[0][wid] = eA; s_red[1][wid] = eB; }
        __syncthreads();
        if (j == 0) {
            float zA = s_red[0][0] + s_red[0][1] + s_red[0][2] + s_red[0][3];
            float zB = s_red[1][0] + s_red[1][1] + s_red[1][2] + s_red[1][3];
            g_res[bA] = (cA + __logf(zA)) - s_gold[0];
            g_res[bB] = (cB + __logf(zB)) - s_gold[1];
        }
    }
}

// deterministic fixed-order mean: shfl-tree (512 = 16 warps -> 16 partials -> warp 0)
__global__ void crf_reduce(float* __restrict__ out) {
    __shared__ float sred[16];
    const int t    = threadIdx.x;
    const int lane = t & 31;
    const int wid  = t >> 5;

    float v = g_res[t];
#pragma unroll
    for (int o = 16; o > 0; o >>= 1) v += __shfl_down_sync(0xffffffffu, v, o);
    if (lane == 0) sred[wid] = v;
    __syncthreads();
    if (wid == 0) {
        float w = (lane < 16) ? sred[lane] : 0.0f;
#pragma unroll
        for (int o = 8; o > 0; o >>= 1) w += __shfl_down_sync(0xffffffffu, w, o);
        if (lane == 0) out[0] = w * (1.0f / (float)BB);
    }
}

extern "C" void kernel_launch(void* const* d_in, const int* in_sizes, int n_in,
                              void* d_out, int out_size) {
    const float* feat = (const float*)d_in[0];
    const int*   tags = (const int*)d_in[1];
    const int*   mask = (const int*)d_in[2];
    const float* tr   = (const float*)d_in[3];

    crf_count<<<BB, 128>>>(mask);
    crf_sort<<<1, BB>>>();
    crf_fwd<<<BB / 2, 128>>>(feat, tags, tr);
    crf_reduce<<<1, BB>>>((float*)d_out);
}